// round 7
// baseline (speedup 1.0000x reference)
#include <cuda_runtime.h>
#include <cuda_fp16.h>
#include <cstring>

#define BATCH 8
#define M 4096
#define NPTS 4096
#define NSLICES 8
#define SLICE (NPTS / NSLICES)               // 512 gt points per block
#define ROWS_PB 32                           // rows per block (4 per warp)
#define RGROUPS (M / ROWS_PB)                // 128
#define NBLOCKS (BATCH * RGROUPS * NSLICES)  // 8192
#define NROWS (BATCH * M)                    // 32768

// f16-exact scale: round_to_f16(10*log2(e)) = 14.4296875.
// ex2 arg: 12 - C*d  =>  e = 2^12 * softmin weight; the 2^12 cancels in w/s.
#define C_F16 14.4296875f

__device__ float g_s[NROWS * NSLICES];   // per-(row, slice) sum of e
__device__ float g_w[NROWS * NSLICES];   // per-(row, slice) sum of e*d
__device__ float g_p2[64];

// Fused tail: two scalar f32 d^2 -> |.| -> sqrt x2 (MUFU) -> f16x2 pack ->
// arg = 12 - C*d -> ex2.f16x2 (MUFU) -> s += e, w += e*d (f16x2 pipes).
// All ops here are guaranteed single SASS instructions on sm_103a.
__device__ __forceinline__ void tail(float d2lo, float d2hi,
                                     unsigned hC, unsigned hB,
                                     unsigned& s, unsigned& w) {
    asm("{\n\t"
        ".reg .f32 alo, ahi, slo, shi;\n\t"
        ".reg .b32 hd, arg, e;\n\t"
        "abs.f32 alo, %2;\n\t"
        "abs.f32 ahi, %3;\n\t"
        "sqrt.approx.f32 slo, alo;\n\t"
        "sqrt.approx.f32 shi, ahi;\n\t"
        "cvt.rn.f16x2.f32 hd, shi, slo;\n\t"
        "fma.rn.f16x2 arg, hd, %4, %5;\n\t"
        "ex2.approx.f16x2 e, arg;\n\t"
        "add.rn.f16x2 %0, %0, e;\n\t"
        "fma.rn.f16x2 %1, e, hd, %1;\n\t"
        "}"
        : "+r"(s), "+r"(w)
        : "f"(d2lo), "f"(d2hi), "r"(hC), "r"(hB));
}

__device__ __forceinline__ void flush_h2(unsigned& h, float& f) {
    __half2 v; memcpy(&v, &h, 4);
    f += __low2float(v) + __high2float(v);
    h = 0u;
}

__global__ __launch_bounds__(256, 4)
void emd_main(const float* __restrict__ pred, const float* __restrict__ gt)
{
    __shared__ __align__(16) float spx[SLICE];
    __shared__ __align__(16) float spy[SLICE];
    __shared__ __align__(16) float spz[SLICE];
    __shared__ __align__(16) float sg2[SLICE];

    const int bid = blockIdx.x;
    const int sl  = bid & (NSLICES - 1);
    const int rg  = (bid >> 3) & (RGROUPS - 1);
    const int b   = bid >> 10;

    // Stage slice with precomputed |g|^2
    const float* g = gt + ((size_t)b * NPTS + (size_t)sl * SLICE) * 3;
    for (int i = threadIdx.x; i < SLICE; i += 256) {
        float x = g[3 * i + 0];
        float y = g[3 * i + 1];
        float z = g[3 * i + 2];
        spx[i] = x; spy[i] = y; spz[i] = z;
        sg2[i] = fmaf(x, x, fmaf(y, y, z * z));
    }
    __syncthreads();

    const int warp = threadIdx.x >> 5;
    const int lane = threadIdx.x & 31;
    const int m0   = rg * ROWS_PB + warp * 4;   // this warp's 4 rows

    // Per-row scalar constants: q = -2p, p2 = |p|^2
    float qx[4], qy[4], qz[4], p2[4];
    const float* p = pred + ((size_t)b * M + m0) * 3;
#pragma unroll
    for (int r = 0; r < 4; r++) {
        float px = __ldg(p + 3 * r + 0);
        float py = __ldg(p + 3 * r + 1);
        float pz = __ldg(p + 3 * r + 2);
        qx[r] = -2.0f * px;
        qy[r] = -2.0f * py;
        qz[r] = -2.0f * pz;
        p2[r] = fmaf(px, px, fmaf(py, py, pz * pz));
    }

    unsigned hC, hB;
    { __half2 t = __float2half2_rn(-C_F16); memcpy(&hC, &t, 4); }
    { __half2 t = __float2half2_rn(12.0f);  memcpy(&hB, &t, 4); }

    unsigned sh[4] = {0u, 0u, 0u, 0u};
    unsigned wh[4] = {0u, 0u, 0u, 0u};
    float sF[4] = {0.f, 0.f, 0.f, 0.f};
    float wF[4] = {0.f, 0.f, 0.f, 0.f};

    // 8 point-pairs per lane: lane L handles points {2L+64j, 2L+64j+1};
    // float2 shared loads give two scalar regs directly (no unpack movs).
#pragma unroll
    for (int j = 0; j < 8; j++) {
        const int n = 2 * lane + 64 * j;
        const float2 ax = *(const float2*)&spx[n];
        const float2 ay = *(const float2*)&spy[n];
        const float2 az = *(const float2*)&spz[n];
        const float2 g2 = *(const float2*)&sg2[n];
#pragma unroll
        for (int r = 0; r < 4; r++) {
            float blo = g2.x + p2[r];
            float bhi = g2.y + p2[r];
            float d2lo = fmaf(qx[r], ax.x, fmaf(qy[r], ay.x, fmaf(qz[r], az.x, blo)));
            float d2hi = fmaf(qx[r], ax.y, fmaf(qy[r], ay.y, fmaf(qz[r], az.y, bhi)));
            tail(d2lo, d2hi, hC, hB, sh[r], wh[r]);
        }
        if (j == 3) {                             // mid flush: <=4 terms/half
#pragma unroll
            for (int r = 0; r < 4; r++) {
                flush_h2(sh[r], sF[r]);
                flush_h2(wh[r], wF[r]);
            }
        }
    }
#pragma unroll
    for (int r = 0; r < 4; r++) {
        flush_h2(sh[r], sF[r]);
        flush_h2(wh[r], wF[r]);
    }

    // Warp-reduce (s, w) per row; this warp owns (row, slice)
#pragma unroll
    for (int r = 0; r < 4; r++) {
        float s = sF[r], w = wF[r];
#pragma unroll
        for (int o = 16; o; o >>= 1) {
            s += __shfl_xor_sync(0xffffffffu, s, o);
            w += __shfl_xor_sync(0xffffffffu, w, o);
        }
        if (lane == 0) {
            const int row = b * M + m0 + r;
            g_s[row * NSLICES + sl] = s;
            g_w[row * NSLICES + sl] = w;
        }
    }
}

__global__ void emd_combine(void)
{
    __shared__ float sm[16];
    const int row = blockIdx.x * 512 + threadIdx.x;   // 64 x 512 = 32768 rows
    float s = 0.0f, w = 0.0f;
#pragma unroll
    for (int k = 0; k < NSLICES; k++) {
        s += g_s[row * NSLICES + k];
        w += g_w[row * NSLICES + k];
    }
    float val = w / s;                    // per-row softmin-weighted distance
#pragma unroll
    for (int o = 16; o; o >>= 1)
        val += __shfl_xor_sync(0xffffffffu, val, o);
    if ((threadIdx.x & 31) == 0) sm[threadIdx.x >> 5] = val;
    __syncthreads();
    if (threadIdx.x < 16) {
        float v = sm[threadIdx.x];
#pragma unroll
        for (int o = 8; o; o >>= 1)
            v += __shfl_xor_sync(0xffffu, v, o);
        if (threadIdx.x == 0) g_p2[blockIdx.x] = v;
    }
}

__global__ void emd_final(float* __restrict__ out)
{
    __shared__ float sm[2];
    float v = g_p2[threadIdx.x];          // 64 threads
#pragma unroll
    for (int o = 16; o; o >>= 1)
        v += __shfl_xor_sync(0xffffffffu, v, o);
    if ((threadIdx.x & 31) == 0) sm[threadIdx.x >> 5] = v;
    __syncthreads();
    if (threadIdx.x == 0)
        out[0] = (sm[0] + sm[1]) * (1.0f / (float)NROWS);   // LOSS_WEIGHT = 1.0
}

extern "C" void kernel_launch(void* const* d_in, const int* in_sizes, int n_in,
                              void* d_out, int out_size)
{
    const float* pred = (const float*)d_in[0];  // [B, M, 3] fp32
    const float* gt   = (const float*)d_in[1];  // [B, N, 3] fp32
    float* out        = (float*)d_out;          // scalar fp32

    emd_main<<<NBLOCKS, 256>>>(pred, gt);
    emd_combine<<<64, 512>>>();
    emd_final<<<1, 64>>>(out);
}

// round 8
// speedup vs baseline: 1.0941x; 1.0941x over previous
#include <cuda_runtime.h>
#include <cuda_fp16.h>
#include <cstring>

#define BATCH 8
#define M 4096
#define NPTS 4096
#define NSLICES 4
#define SLICE (NPTS / NSLICES)               // 1024 gt points per block
#define ROWS_PB 32                           // rows per block (4 per warp)
#define RGROUPS (M / ROWS_PB)                // 128
#define NBLOCKS (BATCH * RGROUPS * NSLICES)  // 4096
#define NROWS (BATCH * M)                    // 32768

// f16-exact scale: round_to_f16(10*log2(e)) = 14.4296875.
// ex2 arg: 12 - C*d  =>  e = 2^12 * softmin weight; the 2^12 cancels in w/s.
#define C_F16 14.4296875f

__device__ float g_s[NROWS * NSLICES];   // per-(row, slice) sum of e
__device__ float g_w[NROWS * NSLICES];   // per-(row, slice) sum of e*d
__device__ float g_p2[64];

// Fused tail: two scalar f32 d^2 -> |.| -> sqrt x2 (MUFU) -> f16x2 pack ->
// arg = 12 - C*d -> ex2.f16x2 (MUFU) -> s += e, w += e*d (f16x2 pipes).
__device__ __forceinline__ void tail(float d2lo, float d2hi,
                                     unsigned hC, unsigned hB,
                                     unsigned& s, unsigned& w) {
    asm("{\n\t"
        ".reg .f32 alo, ahi, slo, shi;\n\t"
        ".reg .b32 hd, arg, e;\n\t"
        "abs.f32 alo, %2;\n\t"
        "abs.f32 ahi, %3;\n\t"
        "sqrt.approx.f32 slo, alo;\n\t"
        "sqrt.approx.f32 shi, ahi;\n\t"
        "cvt.rn.f16x2.f32 hd, shi, slo;\n\t"
        "fma.rn.f16x2 arg, hd, %4, %5;\n\t"
        "ex2.approx.f16x2 e, arg;\n\t"
        "add.rn.f16x2 %0, %0, e;\n\t"
        "fma.rn.f16x2 %1, e, hd, %1;\n\t"
        "}"
        : "+r"(s), "+r"(w)
        : "f"(d2lo), "f"(d2hi), "r"(hC), "r"(hB));
}

__device__ __forceinline__ void flush_h2(unsigned& h, float& f) {
    __half2 v; memcpy(&v, &h, 4);
    f += __low2float(v) + __high2float(v);
    h = 0u;
}

__global__ __launch_bounds__(256, 4)
void emd_main(const float* __restrict__ pred, const float* __restrict__ gt)
{
    __shared__ __align__(16) float spx[SLICE];
    __shared__ __align__(16) float spy[SLICE];
    __shared__ __align__(16) float spz[SLICE];
    __shared__ __align__(16) float sg2[SLICE];

    const int bid = blockIdx.x;
    const int sl  = bid & (NSLICES - 1);
    const int rg  = (bid >> 2) & (RGROUPS - 1);
    const int b   = bid >> 9;

    // Stage slice coalesced: thread t owns points 4t..4t+3 via 3x float4
    {
        const float4* g4 = (const float4*)(gt + ((size_t)b * NPTS + (size_t)sl * SLICE) * 3);
        const int t = threadIdx.x;
        const float4 v0 = g4[3 * t + 0];
        const float4 v1 = g4[3 * t + 1];
        const float4 v2 = g4[3 * t + 2];
        float px[4], py[4], pz[4];
        px[0] = v0.x; py[0] = v0.y; pz[0] = v0.z;
        px[1] = v0.w; py[1] = v1.x; pz[1] = v1.y;
        px[2] = v1.z; py[2] = v1.w; pz[2] = v2.x;
        px[3] = v2.y; py[3] = v2.z; pz[3] = v2.w;
#pragma unroll
        for (int k = 0; k < 4; k++) {
            spx[4 * t + k] = px[k];
            spy[4 * t + k] = py[k];
            spz[4 * t + k] = pz[k];
            sg2[4 * t + k] = fmaf(px[k], px[k], fmaf(py[k], py[k], pz[k] * pz[k]));
        }
    }
    __syncthreads();

    const int warp = threadIdx.x >> 5;
    const int lane = threadIdx.x & 31;
    const int m0   = rg * ROWS_PB + warp * 4;   // this warp's 4 rows

    // Per-row scalar constants: q = -2p, p2 = |p|^2
    float qx[4], qy[4], qz[4], p2[4];
    const float* p = pred + ((size_t)b * M + m0) * 3;
#pragma unroll
    for (int r = 0; r < 4; r++) {
        float px = __ldg(p + 3 * r + 0);
        float py = __ldg(p + 3 * r + 1);
        float pz = __ldg(p + 3 * r + 2);
        qx[r] = -2.0f * px;
        qy[r] = -2.0f * py;
        qz[r] = -2.0f * pz;
        p2[r] = fmaf(px, px, fmaf(py, py, pz * pz));
    }

    unsigned hC, hB;
    { __half2 t = __float2half2_rn(-C_F16); memcpy(&hC, &t, 4); }
    { __half2 t = __float2half2_rn(12.0f);  memcpy(&hB, &t, 4); }

    unsigned sh[4] = {0u, 0u, 0u, 0u};
    unsigned wh[4] = {0u, 0u, 0u, 0u};
    float sF[4] = {0.f, 0.f, 0.f, 0.f};
    float wF[4] = {0.f, 0.f, 0.f, 0.f};

    // 16 point-pairs per lane: lane L handles points {2L+64j, 2L+64j+1}
#pragma unroll
    for (int j = 0; j < 16; j++) {
        const int n = 2 * lane + 64 * j;
        const float2 ax = *(const float2*)&spx[n];
        const float2 ay = *(const float2*)&spy[n];
        const float2 az = *(const float2*)&spz[n];
        const float2 g2 = *(const float2*)&sg2[n];
#pragma unroll
        for (int r = 0; r < 4; r++) {
            float blo = g2.x + p2[r];
            float bhi = g2.y + p2[r];
            float d2lo = fmaf(qx[r], ax.x, fmaf(qy[r], ay.x, fmaf(qz[r], az.x, blo)));
            float d2hi = fmaf(qx[r], ax.y, fmaf(qy[r], ay.y, fmaf(qz[r], az.y, bhi)));
            tail(d2lo, d2hi, hC, hB, sh[r], wh[r]);
        }
        if (j == 7) {                 // single mid flush: <=8 f16 terms/half
#pragma unroll
            for (int r = 0; r < 4; r++) {
                flush_h2(sh[r], sF[r]);
                flush_h2(wh[r], wF[r]);
            }
        }
    }
#pragma unroll
    for (int r = 0; r < 4; r++) {
        flush_h2(sh[r], sF[r]);
        flush_h2(wh[r], wF[r]);
    }

    // Warp-reduce (s, w) per row; this warp owns (row, slice)
#pragma unroll
    for (int r = 0; r < 4; r++) {
        float s = sF[r], w = wF[r];
#pragma unroll
        for (int o = 16; o; o >>= 1) {
            s += __shfl_xor_sync(0xffffffffu, s, o);
            w += __shfl_xor_sync(0xffffffffu, w, o);
        }
        if (lane == 0) {
            const int row = b * M + m0 + r;
            g_s[row * NSLICES + sl] = s;
            g_w[row * NSLICES + sl] = w;
        }
    }
}

__global__ void emd_combine(void)
{
    __shared__ float sm[16];
    const int row = blockIdx.x * 512 + threadIdx.x;   // 64 x 512 = 32768 rows
    float s = 0.0f, w = 0.0f;
#pragma unroll
    for (int k = 0; k < NSLICES; k++) {
        s += g_s[row * NSLICES + k];
        w += g_w[row * NSLICES + k];
    }
    float val = w / s;                    // per-row softmin-weighted distance
#pragma unroll
    for (int o = 16; o; o >>= 1)
        val += __shfl_xor_sync(0xffffffffu, val, o);
    if ((threadIdx.x & 31) == 0) sm[threadIdx.x >> 5] = val;
    __syncthreads();
    if (threadIdx.x < 16) {
        float v = sm[threadIdx.x];
#pragma unroll
        for (int o = 8; o; o >>= 1)
            v += __shfl_xor_sync(0xffffu, v, o);
        if (threadIdx.x == 0) g_p2[blockIdx.x] = v;
    }
}

__global__ void emd_final(float* __restrict__ out)
{
    __shared__ float sm[2];
    float v = g_p2[threadIdx.x];          // 64 threads
#pragma unroll
    for (int o = 16; o; o >>= 1)
        v += __shfl_xor_sync(0xffffffffu, v, o);
    if ((threadIdx.x & 31) == 0) sm[threadIdx.x >> 5] = v;
    __syncthreads();
    if (threadIdx.x == 0)
        out[0] = (sm[0] + sm[1]) * (1.0f / (float)NROWS);   // LOSS_WEIGHT = 1.0
}

extern "C" void kernel_launch(void* const* d_in, const int* in_sizes, int n_in,
                              void* d_out, int out_size)
{
    const float* pred = (const float*)d_in[0];  // [B, M, 3] fp32
    const float* gt   = (const float*)d_in[1];  // [B, N, 3] fp32
    float* out        = (float*)d_out;          // scalar fp32

    emd_main<<<NBLOCKS, 256>>>(pred, gt);
    emd_combine<<<64, 512>>>();
    emd_final<<<1, 64>>>(out);
}

// round 9
// speedup vs baseline: 1.1855x; 1.0835x over previous
#include <cuda_runtime.h>
#include <cuda_fp16.h>
#include <cstring>

#define BATCH 8
#define M 4096
#define NPTS 4096
#define NSLICES 4
#define SLICE (NPTS / NSLICES)               // 1024 gt points per block
#define ROWS_PB 32                           // rows per block (4 per warp)
#define RGROUPS (M / ROWS_PB)                // 128
#define NBLOCKS (BATCH * RGROUPS * NSLICES)  // 4096
#define NROWS (BATCH * M)                    // 32768

// f16-exact scale: round_to_f16(10*log2(e)) = 14.4296875.
// ex2 arg: 12 - C*d  =>  e = 2^12 * softmin weight; the 2^12 cancels in w/s.
#define C_F16 14.4296875f
// Bias folded into p2 so the fma-chain d^2 is provably >= 0 (chain rounding
// error <= ~4e-6); lets sqrt.approx run without abs/clamp. delta-d <= 1e-4
// at d ~ 0.1 -> negligible.
#define D2_BIAS 2e-5f

__device__ float g_s[NROWS * NSLICES];   // per-(row, slice) sum of e
__device__ float g_w[NROWS * NSLICES];   // per-(row, slice) sum of e*d
__device__ float g_p2[64];

// Fused tail: two scalar f32 d^2 (>=0 by construction) -> sqrt x2 (MUFU) ->
// f16x2 pack -> arg = 12 - C*d -> ex2.f16x2 (MUFU) -> s += e, w += e*d.
__device__ __forceinline__ void tail(float d2lo, float d2hi,
                                     unsigned hC, unsigned hB,
                                     unsigned& s, unsigned& w) {
    asm("{\n\t"
        ".reg .f32 slo, shi;\n\t"
        ".reg .b32 hd, arg, e;\n\t"
        "sqrt.approx.f32 slo, %2;\n\t"
        "sqrt.approx.f32 shi, %3;\n\t"
        "cvt.rn.f16x2.f32 hd, shi, slo;\n\t"
        "fma.rn.f16x2 arg, hd, %4, %5;\n\t"
        "ex2.approx.f16x2 e, arg;\n\t"
        "add.rn.f16x2 %0, %0, e;\n\t"
        "fma.rn.f16x2 %1, e, hd, %1;\n\t"
        "}"
        : "+r"(s), "+r"(w)
        : "f"(d2lo), "f"(d2hi), "r"(hC), "r"(hB));
}

__device__ __forceinline__ void flush_h2(unsigned& h, float& f) {
    __half2 v; memcpy(&v, &h, 4);
    f += __low2float(v) + __high2float(v);
    h = 0u;
}

__global__ __launch_bounds__(256, 4)
void emd_main(const float* __restrict__ pred, const float* __restrict__ gt)
{
    // AoS: one float4 {x, y, z, |g|^2} per gt point -> 2x LDS.128 per pair
    __shared__ __align__(16) float4 sPt[SLICE];

    const int bid = blockIdx.x;
    const int sl  = bid & (NSLICES - 1);
    const int rg  = (bid >> 2) & (RGROUPS - 1);
    const int b   = bid >> 9;

    // Stage slice coalesced: thread t owns points 4t..4t+3 via 3x float4
    {
        const float4* g4 = (const float4*)(gt + ((size_t)b * NPTS + (size_t)sl * SLICE) * 3);
        const int t = threadIdx.x;
        const float4 v0 = g4[3 * t + 0];
        const float4 v1 = g4[3 * t + 1];
        const float4 v2 = g4[3 * t + 2];
        float px[4], py[4], pz[4];
        px[0] = v0.x; py[0] = v0.y; pz[0] = v0.z;
        px[1] = v0.w; py[1] = v1.x; pz[1] = v1.y;
        px[2] = v1.z; py[2] = v1.w; pz[2] = v2.x;
        px[3] = v2.y; py[3] = v2.z; pz[3] = v2.w;
#pragma unroll
        for (int k = 0; k < 4; k++) {
            float g2 = fmaf(px[k], px[k], fmaf(py[k], py[k], pz[k] * pz[k]));
            sPt[4 * t + k] = make_float4(px[k], py[k], pz[k], g2);
        }
    }
    __syncthreads();

    const int warp = threadIdx.x >> 5;
    const int lane = threadIdx.x & 31;
    const int m0   = rg * ROWS_PB + warp * 4;   // this warp's 4 rows

    // Per-row scalar constants: q = -2p, p2 = |p|^2 + bias
    float qx[4], qy[4], qz[4], p2[4];
    const float* p = pred + ((size_t)b * M + m0) * 3;
#pragma unroll
    for (int r = 0; r < 4; r++) {
        float px = __ldg(p + 3 * r + 0);
        float py = __ldg(p + 3 * r + 1);
        float pz = __ldg(p + 3 * r + 2);
        qx[r] = -2.0f * px;
        qy[r] = -2.0f * py;
        qz[r] = -2.0f * pz;
        p2[r] = fmaf(px, px, fmaf(py, py, pz * pz)) + D2_BIAS;
    }

    unsigned hC, hB;
    { __half2 t = __float2half2_rn(-C_F16); memcpy(&hC, &t, 4); }
    { __half2 t = __float2half2_rn(12.0f);  memcpy(&hB, &t, 4); }

    unsigned sh[4] = {0u, 0u, 0u, 0u};
    unsigned wh[4] = {0u, 0u, 0u, 0u};
    float sF[4] = {0.f, 0.f, 0.f, 0.f};
    float wF[4] = {0.f, 0.f, 0.f, 0.f};

    // 16 point-pairs per lane: lane L handles points {2L+64j, 2L+64j+1}
#pragma unroll
    for (int j = 0; j < 16; j++) {
        const int n = 2 * lane + 64 * j;
        const float4 P0 = sPt[n];
        const float4 P1 = sPt[n + 1];
#pragma unroll
        for (int r = 0; r < 4; r++) {
            float blo = P0.w + p2[r];
            float bhi = P1.w + p2[r];
            float d2lo = fmaf(qx[r], P0.x, fmaf(qy[r], P0.y, fmaf(qz[r], P0.z, blo)));
            float d2hi = fmaf(qx[r], P1.x, fmaf(qy[r], P1.y, fmaf(qz[r], P1.z, bhi)));
            tail(d2lo, d2hi, hC, hB, sh[r], wh[r]);
        }
        if (j == 7) {                 // single mid flush: <=8 f16 terms/half
#pragma unroll
            for (int r = 0; r < 4; r++) {
                flush_h2(sh[r], sF[r]);
                flush_h2(wh[r], wF[r]);
            }
        }
    }
#pragma unroll
    for (int r = 0; r < 4; r++) {
        flush_h2(sh[r], sF[r]);
        flush_h2(wh[r], wF[r]);
    }

    // Warp-reduce (s, w) per row; this warp owns (row, slice)
#pragma unroll
    for (int r = 0; r < 4; r++) {
        float s = sF[r], w = wF[r];
#pragma unroll
        for (int o = 16; o; o >>= 1) {
            s += __shfl_xor_sync(0xffffffffu, s, o);
            w += __shfl_xor_sync(0xffffffffu, w, o);
        }
        if (lane == 0) {
            const int row = b * M + m0 + r;
            g_s[row * NSLICES + sl] = s;
            g_w[row * NSLICES + sl] = w;
        }
    }
}

__global__ void emd_combine(void)
{
    __shared__ float sm[16];
    const int row = blockIdx.x * 512 + threadIdx.x;   // 64 x 512 = 32768 rows
    float s = 0.0f, w = 0.0f;
#pragma unroll
    for (int k = 0; k < NSLICES; k++) {
        s += g_s[row * NSLICES + k];
        w += g_w[row * NSLICES + k];
    }
    float val = w / s;                    // per-row softmin-weighted distance
#pragma unroll
    for (int o = 16; o; o >>= 1)
        val += __shfl_xor_sync(0xffffffffu, val, o);
    if ((threadIdx.x & 31) == 0) sm[threadIdx.x >> 5] = val;
    __syncthreads();
    if (threadIdx.x < 16) {
        float v = sm[threadIdx.x];
#pragma unroll
        for (int o = 8; o; o >>= 1)
            v += __shfl_xor_sync(0xffffu, v, o);
        if (threadIdx.x == 0) g_p2[blockIdx.x] = v;
    }
}

__global__ void emd_final(float* __restrict__ out)
{
    __shared__ float sm[2];
    float v = g_p2[threadIdx.x];          // 64 threads
#pragma unroll
    for (int o = 16; o; o >>= 1)
        v += __shfl_xor_sync(0xffffffffu, v, o);
    if ((threadIdx.x & 31) == 0) sm[threadIdx.x >> 5] = v;
    __syncthreads();
    if (threadIdx.x == 0)
        out[0] = (sm[0] + sm[1]) * (1.0f / (float)NROWS);   // LOSS_WEIGHT = 1.0
}

extern "C" void kernel_launch(void* const* d_in, const int* in_sizes, int n_in,
                              void* d_out, int out_size)
{
    const float* pred = (const float*)d_in[0];  // [B, M, 3] fp32
    const float* gt   = (const float*)d_in[1];  // [B, N, 3] fp32
    float* out        = (float*)d_out;          // scalar fp32

    emd_main<<<NBLOCKS, 256>>>(pred, gt);
    emd_combine<<<64, 512>>>();
    emd_final<<<1, 64>>>(out);
}

// round 10
// speedup vs baseline: 1.1945x; 1.0076x over previous
#include <cuda_runtime.h>
#include <cuda_fp16.h>
#include <cstring>

#define BATCH 8
#define M 4096
#define NPTS 4096
#define NSLICES 4
#define SLICE (NPTS / NSLICES)               // 1024 gt points per block
#define ROWS_PB 32                           // rows per block (4 per warp)
#define RGROUPS (M / ROWS_PB)                // 128
#define NBLOCKS (BATCH * RGROUPS * NSLICES)  // 4096
#define NROWS (BATCH * M)                    // 32768

// f16-exact scale: round_to_f16(10*log2(e)) = 14.4296875.
// ex2 arg: 12 - C*d  =>  e = 2^12 * softmin weight; the 2^12 cancels in w/s.
#define C_F16 14.4296875f
// Bias folded into p2 so the fma-chain d^2 is provably >= 0 (chain rounding
// error <= ~4e-6); lets sqrt.approx run without abs/clamp.
#define D2_BIAS 2e-5f

__device__ float g_s[NROWS * NSLICES];   // per-(row, slice) sum of e
__device__ float g_w[NROWS * NSLICES];   // per-(row, slice) sum of e*d
__device__ float g_p2[64];

// Fused tail: two scalar f32 d^2 (>=0 by construction) -> sqrt x2 (MUFU) ->
// f16x2 pack -> arg = 12 - C*d -> ex2.f16x2 (MUFU) -> s += e, w += e*d.
__device__ __forceinline__ void tail(float d2lo, float d2hi,
                                     unsigned hC, unsigned hB,
                                     unsigned& s, unsigned& w) {
    asm("{\n\t"
        ".reg .f32 slo, shi;\n\t"
        ".reg .b32 hd, arg, e;\n\t"
        "sqrt.approx.f32 slo, %2;\n\t"
        "sqrt.approx.f32 shi, %3;\n\t"
        "cvt.rn.f16x2.f32 hd, shi, slo;\n\t"
        "fma.rn.f16x2 arg, hd, %4, %5;\n\t"
        "ex2.approx.f16x2 e, arg;\n\t"
        "add.rn.f16x2 %0, %0, e;\n\t"
        "fma.rn.f16x2 %1, e, hd, %1;\n\t"
        "}"
        : "+r"(s), "+r"(w)
        : "f"(d2lo), "f"(d2hi), "r"(hC), "r"(hB));
}

__device__ __forceinline__ void flush_h2(unsigned& h, float& f) {
    __half2 v; memcpy(&v, &h, 4);
    f += __low2float(v) + __high2float(v);
    h = 0u;
}

__global__ __launch_bounds__(256, 4)
void emd_main(const float* __restrict__ pred, const float* __restrict__ gt)
{
    // AoS: one float4 {x, y, z, |g|^2} per gt point
    __shared__ __align__(16) float4 sPt[SLICE];

    const int bid = blockIdx.x;
    const int sl  = bid & (NSLICES - 1);
    const int rg  = (bid >> 2) & (RGROUPS - 1);
    const int b   = bid >> 9;

    // Stage slice coalesced: thread t owns points 4t..4t+3 via 3x float4
    {
        const float4* g4 = (const float4*)(gt + ((size_t)b * NPTS + (size_t)sl * SLICE) * 3);
        const int t = threadIdx.x;
        const float4 v0 = g4[3 * t + 0];
        const float4 v1 = g4[3 * t + 1];
        const float4 v2 = g4[3 * t + 2];
        float px[4], py[4], pz[4];
        px[0] = v0.x; py[0] = v0.y; pz[0] = v0.z;
        px[1] = v0.w; py[1] = v1.x; pz[1] = v1.y;
        px[2] = v1.z; py[2] = v1.w; pz[2] = v2.x;
        px[3] = v2.y; py[3] = v2.z; pz[3] = v2.w;
#pragma unroll
        for (int k = 0; k < 4; k++) {
            float g2 = fmaf(px[k], px[k], fmaf(py[k], py[k], pz[k] * pz[k]));
            sPt[4 * t + k] = make_float4(px[k], py[k], pz[k], g2);
        }
    }
    __syncthreads();

    const int warp = threadIdx.x >> 5;
    const int lane = threadIdx.x & 31;
    const int m0   = rg * ROWS_PB + warp * 4;   // this warp's 4 rows

    // Per-row scalar constants: q = -2p, p2 = |p|^2 + bias
    float qx[4], qy[4], qz[4], p2[4];
    const float* p = pred + ((size_t)b * M + m0) * 3;
#pragma unroll
    for (int r = 0; r < 4; r++) {
        float px = __ldg(p + 3 * r + 0);
        float py = __ldg(p + 3 * r + 1);
        float pz = __ldg(p + 3 * r + 2);
        qx[r] = -2.0f * px;
        qy[r] = -2.0f * py;
        qz[r] = -2.0f * pz;
        p2[r] = fmaf(px, px, fmaf(py, py, pz * pz)) + D2_BIAS;
    }

    unsigned hC, hB;
    { __half2 t = __float2half2_rn(-C_F16); memcpy(&hC, &t, 4); }
    { __half2 t = __float2half2_rn(12.0f);  memcpy(&hB, &t, 4); }

    unsigned sh[4] = {0u, 0u, 0u, 0u};
    unsigned wh[4] = {0u, 0u, 0u, 0u};
    float sF[4] = {0.f, 0.f, 0.f, 0.f};
    float wF[4] = {0.f, 0.f, 0.f, 0.f};

    // Conflict-free mapping: lane L handles points {L+64j, L+32+64j}.
    // Each LDS.128 is 16B-stride contiguous across the warp (4 clean 128B
    // phases, conflict degree 1).
#pragma unroll
    for (int j = 0; j < 16; j++) {
        const int n = lane + 64 * j;
        const float4 P0 = sPt[n];
        const float4 P1 = sPt[n + 32];
#pragma unroll
        for (int r = 0; r < 4; r++) {
            float blo = P0.w + p2[r];
            float bhi = P1.w + p2[r];
            float d2lo = fmaf(qx[r], P0.x, fmaf(qy[r], P0.y, fmaf(qz[r], P0.z, blo)));
            float d2hi = fmaf(qx[r], P1.x, fmaf(qy[r], P1.y, fmaf(qz[r], P1.z, bhi)));
            tail(d2lo, d2hi, hC, hB, sh[r], wh[r]);
        }
        if (j == 7) {                 // single mid flush: <=8 f16 terms/half
#pragma unroll
            for (int r = 0; r < 4; r++) {
                flush_h2(sh[r], sF[r]);
                flush_h2(wh[r], wF[r]);
            }
        }
    }
#pragma unroll
    for (int r = 0; r < 4; r++) {
        flush_h2(sh[r], sF[r]);
        flush_h2(wh[r], wF[r]);
    }

    // Warp-reduce (s, w) per row; this warp owns (row, slice)
#pragma unroll
    for (int r = 0; r < 4; r++) {
        float s = sF[r], w = wF[r];
#pragma unroll
        for (int o = 16; o; o >>= 1) {
            s += __shfl_xor_sync(0xffffffffu, s, o);
            w += __shfl_xor_sync(0xffffffffu, w, o);
        }
        if (lane == 0) {
            const int row = b * M + m0 + r;
            g_s[row * NSLICES + sl] = s;
            g_w[row * NSLICES + sl] = w;
        }
    }
}

__global__ void emd_combine(void)
{
    __shared__ float sm[16];
    const int row = blockIdx.x * 512 + threadIdx.x;   // 64 x 512 = 32768 rows
    float s = 0.0f, w = 0.0f;
#pragma unroll
    for (int k = 0; k < NSLICES; k++) {
        s += g_s[row * NSLICES + k];
        w += g_w[row * NSLICES + k];
    }
    float val = w / s;                    // per-row softmin-weighted distance
#pragma unroll
    for (int o = 16; o; o >>= 1)
        val += __shfl_xor_sync(0xffffffffu, val, o);
    if ((threadIdx.x & 31) == 0) sm[threadIdx.x >> 5] = val;
    __syncthreads();
    if (threadIdx.x < 16) {
        float v = sm[threadIdx.x];
#pragma unroll
        for (int o = 8; o; o >>= 1)
            v += __shfl_xor_sync(0xffffu, v, o);
        if (threadIdx.x == 0) g_p2[blockIdx.x] = v;
    }
}

__global__ void emd_final(float* __restrict__ out)
{
    __shared__ float sm[2];
    float v = g_p2[threadIdx.x];          // 64 threads
#pragma unroll
    for (int o = 16; o; o >>= 1)
        v += __shfl_xor_sync(0xffffffffu, v, o);
    if ((threadIdx.x & 31) == 0) sm[threadIdx.x >> 5] = v;
    __syncthreads();
    if (threadIdx.x == 0)
        out[0] = (sm[0] + sm[1]) * (1.0f / (float)NROWS);   // LOSS_WEIGHT = 1.0
}

extern "C" void kernel_launch(void* const* d_in, const int* in_sizes, int n_in,
                              void* d_out, int out_size)
{
    const float* pred = (const float*)d_in[0];  // [B, M, 3] fp32
    const float* gt   = (const float*)d_in[1];  // [B, N, 3] fp32
    float* out        = (float*)d_out;          // scalar fp32

    emd_main<<<NBLOCKS, 256>>>(pred, gt);
    emd_combine<<<64, 512>>>();
    emd_final<<<1, 64>>>(out);
}